// round 1
// baseline (speedup 1.0000x reference)
#include <cuda_runtime.h>

// ---------------------------------------------------------------------------
// CLIPDecoder_83786222011049 — single-head MHA forward, fp32 baseline.
//   q = (query @ Wq^T + bq) * E^-0.5        (16384 x 1024 x 1024)
//   k = key   @ Wk^T + bk                   (16384 x 1024 x 1024)
//   v = value @ Wv^T + bv                   (16384 x 1024 x 1024)
//   scores[n] = q[:,n,:] @ k[:,n,:]^T       (16 x 1024 x 1024 x 1024)
//   attn = softmax(scores, axis=-1)
//   out[:,n,:] = attn[n] @ v[:,n,:]         (16 x 1024 x 1024 x 1024)
// ---------------------------------------------------------------------------

static constexpr int L_DIM   = 1024;
static constexpr int S_DIM   = 1024;
static constexpr int N_BATCH = 16;
static constexpr int E_DIM   = 1024;

// Scratch (device globals — no runtime allocation allowed).
__device__ float g_q[(size_t)L_DIM * N_BATCH * E_DIM];
__device__ float g_k[(size_t)S_DIM * N_BATCH * E_DIM];
__device__ float g_v[(size_t)S_DIM * N_BATCH * E_DIM];
__device__ float g_scores[(size_t)N_BATCH * L_DIM * S_DIM];

// ---------------------------------------------------------------------------
// Tiled GEMM, C = A * B^T (+bias) * scale.  A: MxK (row-major, lda),
// B: NxK (row-major, ldb) -> both K-contiguous.  Batched over blockIdx.z.
// BM=BN=64, BK=16, 256 threads, 4x4 microtile per thread.
// All problem dims here are multiples of the tile sizes -> no bounds checks.
// ---------------------------------------------------------------------------
static constexpr int BM = 64, BN = 64, BK = 16;
static constexpr int BMP = 68, BNP = 68;  // pad: float4-aligned LDS, spread STS banks

__global__ __launch_bounds__(256) void gemm_nt_kernel(
    const float* __restrict__ A, const float* __restrict__ B,
    float* __restrict__ C, const float* __restrict__ bias,
    int K, long long lda, long long ldb, long long ldc,
    long long sA, long long sB, long long sC, float scale)
{
    __shared__ float As[BK][BMP];
    __shared__ float Bs[BK][BNP];

    const int t  = threadIdx.x;
    const int tx = t & 15;
    const int ty = t >> 4;
    const long long m0 = (long long)blockIdx.y * BM;
    const long long n0 = (long long)blockIdx.x * BN;

    const float* Ab = A + (long long)blockIdx.z * sA;
    const float* Bb = B + (long long)blockIdx.z * sB;
    float*       Cb = C + (long long)blockIdx.z * sC;

    const int lrow = t >> 2;        // 0..63 : tile row loaded by this thread
    const int lkv  = (t & 3) * 4;   // 0,4,8,12 : k-offset (float4)

    float acc[4][4] = {};

    for (int k0 = 0; k0 < K; k0 += BK) {
        float4 av = *(const float4*)(Ab + (m0 + lrow) * lda + k0 + lkv);
        float4 bv = *(const float4*)(Bb + (n0 + lrow) * ldb + k0 + lkv);
        __syncthreads();
        As[lkv + 0][lrow] = av.x; As[lkv + 1][lrow] = av.y;
        As[lkv + 2][lrow] = av.z; As[lkv + 3][lrow] = av.w;
        Bs[lkv + 0][lrow] = bv.x; Bs[lkv + 1][lrow] = bv.y;
        Bs[lkv + 2][lrow] = bv.z; Bs[lkv + 3][lrow] = bv.w;
        __syncthreads();

        #pragma unroll
        for (int kk = 0; kk < BK; ++kk) {
            float4 ra = *(const float4*)&As[kk][ty * 4];
            float4 rb = *(const float4*)&Bs[kk][tx * 4];
            float a[4] = {ra.x, ra.y, ra.z, ra.w};
            float b[4] = {rb.x, rb.y, rb.z, rb.w};
            #pragma unroll
            for (int i = 0; i < 4; ++i)
                #pragma unroll
                for (int j = 0; j < 4; ++j)
                    acc[i][j] = fmaf(a[i], b[j], acc[i][j]);
        }
    }

    #pragma unroll
    for (int i = 0; i < 4; ++i) {
        const long long m = m0 + ty * 4 + i;
        #pragma unroll
        for (int j = 0; j < 4; ++j) {
            const long long n = n0 + tx * 4 + j;
            float bsv = bias ? bias[n] : 0.0f;
            Cb[m * ldc + n] = (acc[i][j] + bsv) * scale;
        }
    }
}

// ---------------------------------------------------------------------------
// Tiled GEMM, C = A * B.  A: MxK (row-major, lda), B: KxN (row-major, ldb).
// Same tiling; only the B tile load differs (N-contiguous rows).
// ---------------------------------------------------------------------------
__global__ __launch_bounds__(256) void gemm_nn_kernel(
    const float* __restrict__ A, const float* __restrict__ B,
    float* __restrict__ C,
    int K, long long lda, long long ldb, long long ldc,
    long long sA, long long sB, long long sC)
{
    __shared__ float As[BK][BMP];
    __shared__ float Bs[BK][BNP];

    const int t  = threadIdx.x;
    const int tx = t & 15;
    const int ty = t >> 4;
    const long long m0 = (long long)blockIdx.y * BM;
    const long long n0 = (long long)blockIdx.x * BN;

    const float* Ab = A + (long long)blockIdx.z * sA;
    const float* Bb = B + (long long)blockIdx.z * sB;
    float*       Cb = C + (long long)blockIdx.z * sC;

    const int arow = t >> 2;        // 0..63
    const int akv  = (t & 3) * 4;   // 0,4,8,12
    const int brow = t >> 4;        // 0..15 (k within tile)
    const int bnv  = (t & 15) * 4;  // 0..60

    float acc[4][4] = {};

    for (int k0 = 0; k0 < K; k0 += BK) {
        float4 av = *(const float4*)(Ab + (m0 + arow) * lda + k0 + akv);
        float4 bv = *(const float4*)(Bb + (long long)(k0 + brow) * ldb + n0 + bnv);
        __syncthreads();
        As[akv + 0][arow] = av.x; As[akv + 1][arow] = av.y;
        As[akv + 2][arow] = av.z; As[akv + 3][arow] = av.w;
        *(float4*)&Bs[brow][bnv] = bv;
        __syncthreads();

        #pragma unroll
        for (int kk = 0; kk < BK; ++kk) {
            float4 ra = *(const float4*)&As[kk][ty * 4];
            float4 rb = *(const float4*)&Bs[kk][tx * 4];
            float a[4] = {ra.x, ra.y, ra.z, ra.w};
            float b[4] = {rb.x, rb.y, rb.z, rb.w};
            #pragma unroll
            for (int i = 0; i < 4; ++i)
                #pragma unroll
                for (int j = 0; j < 4; ++j)
                    acc[i][j] = fmaf(a[i], b[j], acc[i][j]);
        }
    }

    #pragma unroll
    for (int i = 0; i < 4; ++i) {
        const long long m = m0 + ty * 4 + i;
        #pragma unroll
        for (int j = 0; j < 4; ++j) {
            const long long n = n0 + tx * 4 + j;
            Cb[m * ldc + n] = acc[i][j];
        }
    }
}

// ---------------------------------------------------------------------------
// Row softmax over S_DIM=1024, one block (256 threads) per row, in place.
// ---------------------------------------------------------------------------
__global__ __launch_bounds__(256) void softmax_kernel(float* __restrict__ scores)
{
    const long long row = blockIdx.x;
    float* p = scores + row * (long long)S_DIM;
    const int t = threadIdx.x;

    float4 v = ((const float4*)p)[t];

    // --- max ---
    float m = fmaxf(fmaxf(v.x, v.y), fmaxf(v.z, v.w));
    #pragma unroll
    for (int o = 16; o > 0; o >>= 1)
        m = fmaxf(m, __shfl_xor_sync(0xFFFFFFFFu, m, o));
    __shared__ float smax[8];
    __shared__ float ssum[8];
    if ((t & 31) == 0) smax[t >> 5] = m;
    __syncthreads();
    float rowmax = smax[0];
    #pragma unroll
    for (int i = 1; i < 8; ++i) rowmax = fmaxf(rowmax, smax[i]);

    // --- exp + sum ---
    v.x = expf(v.x - rowmax);
    v.y = expf(v.y - rowmax);
    v.z = expf(v.z - rowmax);
    v.w = expf(v.w - rowmax);
    float s = v.x + v.y + v.z + v.w;
    #pragma unroll
    for (int o = 16; o > 0; o >>= 1)
        s += __shfl_xor_sync(0xFFFFFFFFu, s, o);
    if ((t & 31) == 0) ssum[t >> 5] = s;
    __syncthreads();
    float rowsum = 0.0f;
    #pragma unroll
    for (int i = 0; i < 8; ++i) rowsum += ssum[i];

    const float inv = 1.0f / rowsum;
    v.x *= inv; v.y *= inv; v.z *= inv; v.w *= inv;
    ((float4*)p)[t] = v;
}

// ---------------------------------------------------------------------------
// Launch
// ---------------------------------------------------------------------------
extern "C" void kernel_launch(void* const* d_in, const int* in_sizes, int n_in,
                              void* d_out, int out_size)
{
    const float* query = (const float*)d_in[0];
    const float* key   = (const float*)d_in[1];
    const float* value = (const float*)d_in[2];
    const float* wq    = (const float*)d_in[3];
    const float* wk    = (const float*)d_in[4];
    const float* wv    = (const float*)d_in[5];
    const float* bias  = (const float*)d_in[6];
    float* out = (float*)d_out;

    float *q, *k, *v, *sc;
    cudaGetSymbolAddress((void**)&q,  g_q);
    cudaGetSymbolAddress((void**)&k,  g_k);
    cudaGetSymbolAddress((void**)&v,  g_v);
    cudaGetSymbolAddress((void**)&sc, g_scores);

    const long long NE = (long long)N_BATCH * E_DIM;
    const long long LS = (long long)L_DIM * S_DIM;
    const float scaling = 1.0f / 32.0f;  // E^-0.5, E = 1024

    // Projections: M = L*N = 16384 rows, N(cols) = E = 1024, K = E.
    {
        dim3 grid(E_DIM / BN, (L_DIM * N_BATCH) / BM, 1);
        gemm_nt_kernel<<<grid, 256>>>(query, wq, q, bias,
                                      E_DIM, E_DIM, E_DIM, E_DIM, 0, 0, 0, scaling);
        gemm_nt_kernel<<<grid, 256>>>(key,   wk, k, bias + E_DIM,
                                      E_DIM, E_DIM, E_DIM, E_DIM, 0, 0, 0, 1.0f);
        gemm_nt_kernel<<<grid, 256>>>(value, wv, v, bias + 2 * E_DIM,
                                      E_DIM, E_DIM, E_DIM, E_DIM, 0, 0, 0, 1.0f);
    }

    // scores[n] = q[:,n,:] @ k[:,n,:]^T   (batched over n via blockIdx.z)
    {
        dim3 grid(S_DIM / BN, L_DIM / BM, N_BATCH);
        gemm_nt_kernel<<<grid, 256>>>(q, k, sc, nullptr,
                                      E_DIM, NE, NE, S_DIM,
                                      E_DIM, E_DIM, LS, 1.0f);
    }

    // softmax over last dim, in place
    softmax_kernel<<<N_BATCH * L_DIM, 256>>>(sc);

    // out[:,n,:] = attn[n] @ v[:,n,:]
    {
        dim3 grid(E_DIM / BN, L_DIM / BM, N_BATCH);
        gemm_nn_kernel<<<grid, 256>>>(sc, v, out,
                                      S_DIM, S_DIM, NE, NE,
                                      LS, E_DIM, E_DIM);
    }
}

// round 2
// speedup vs baseline: 1.7614x; 1.7614x over previous
#include <cuda_runtime.h>
#include <cstdint>

// ---------------------------------------------------------------------------
// CLIPDecoder_83786222011049 — single-head MHA forward.
// Round 2: all GEMMs on tensor cores via 3xTF32 mma.sync (m16n8k8),
// cp.async 3-stage pipeline, 128x128x32 tiles.
// ---------------------------------------------------------------------------

static constexpr int L_DIM   = 1024;
static constexpr int S_DIM   = 1024;
static constexpr int N_BATCH = 16;
static constexpr int E_DIM   = 1024;

__device__ float g_q[(size_t)L_DIM * N_BATCH * E_DIM];
__device__ float g_k[(size_t)S_DIM * N_BATCH * E_DIM];
__device__ float g_v[(size_t)S_DIM * N_BATCH * E_DIM];
__device__ float g_scores[(size_t)N_BATCH * L_DIM * S_DIM];

static constexpr int BM = 128, BN = 128, BK = 32, STAGES = 3;

// SMEM layouts (floats). Strides chosen for conflict-free fragment LDS:
//   k-contig rows, stride 36:  bank = (4*g + q) % 32  -> distinct over warp
//   n-contig rows, stride 136: bank = (8*q + g) % 32  -> distinct over warp
static constexpr int A_STRIDE = 36;
static constexpr int A_F      = BM * A_STRIDE;     // 4608
static constexpr int BT_F     = BN * A_STRIDE;     // 4608 (nt B, k-contig)
static constexpr int STAGE_NT = A_F + BT_F;        // 9216 floats
static constexpr int BN_STRIDE = 136;
static constexpr int BNN_F    = BK * BN_STRIDE;    // 4352 (nn B, n-contig)
static constexpr int STAGE_NN = A_F + BNN_F;       // 8960 floats

// ---------------------------------------------------------------------------
// PTX helpers
// ---------------------------------------------------------------------------
__device__ __forceinline__ uint32_t f2tf(float x) {
    uint32_t r;
    asm("cvt.rna.tf32.f32 %0, %1;" : "=r"(r) : "f"(x));
    return r;
}
// 3xTF32 split: x = hi + lo with hi = rna_tf32(x), lo = rna_tf32(x - hi).
__device__ __forceinline__ void split_tf(float x, uint32_t& hi, uint32_t& lo) {
    hi = f2tf(x);
    lo = f2tf(x - __uint_as_float(hi));
}
__device__ __forceinline__ void mma8(float* d, const uint32_t* a, const uint32_t* b) {
    asm volatile(
        "mma.sync.aligned.m16n8k8.row.col.f32.tf32.tf32.f32 "
        "{%0,%1,%2,%3},{%4,%5,%6,%7},{%8,%9},{%0,%1,%2,%3};\n"
        : "+f"(d[0]), "+f"(d[1]), "+f"(d[2]), "+f"(d[3])
        : "r"(a[0]), "r"(a[1]), "r"(a[2]), "r"(a[3]), "r"(b[0]), "r"(b[1]));
}
__device__ __forceinline__ void cp16(float* sdst, const float* gsrc) {
    uint32_t s = (uint32_t)__cvta_generic_to_shared(sdst);
    asm volatile("cp.async.cg.shared.global [%0], [%1], 16;\n" :: "r"(s), "l"(gsrc));
}
__device__ __forceinline__ void cp_commit() {
    asm volatile("cp.async.commit_group;\n" ::: "memory");
}
template <int N>
__device__ __forceinline__ void cp_wait() {
    asm volatile("cp.async.wait_group %0;\n" :: "n"(N) : "memory");
}

extern __shared__ float dynsmem[];

// ---------------------------------------------------------------------------
// C = (A * B^T + bias) * scale.  A: MxK row-major (lda), B: NxK row-major
// (ldb) — both K-contiguous.  Batched over blockIdx.z.
// ---------------------------------------------------------------------------
__global__ __launch_bounds__(256) void gemm_nt_tc(
    const float* __restrict__ A, const float* __restrict__ B,
    float* __restrict__ C, const float* __restrict__ bias,
    int K, long long lda, long long ldb, long long ldc,
    long long sA, long long sB, long long sC, float scale)
{
    const int tid = threadIdx.x, lane = tid & 31, warp = tid >> 5;
    const int wm = warp & 1, wn = warp >> 1;       // 2 x 4 warp grid
    const int q = lane & 3, g = lane >> 2;

    const long long m0 = (long long)blockIdx.y * BM;
    const long long n0 = (long long)blockIdx.x * BN;
    const float* Ab = A + (long long)blockIdx.z * sA + m0 * lda;
    const float* Bb = B + (long long)blockIdx.z * sB + n0 * ldb;
    float*       Cb = C + (long long)blockIdx.z * sC;

    const int lr = tid >> 3;          // 0..31  (tile row this thread loads)
    const int lk = (tid & 7) * 4;     // k float offset (16B chunks)

    float acc[4][4][4];
    #pragma unroll
    for (int i = 0; i < 4; ++i)
        #pragma unroll
        for (int j = 0; j < 4; ++j)
            #pragma unroll
            for (int r = 0; r < 4; ++r) acc[i][j][r] = 0.0f;

    const int KT = K / BK;

    auto load_tile = [&](int kt) {
        float* As = dynsmem + (kt % STAGES) * STAGE_NT;
        float* Bs = As + A_F;
        const float* Ag = Ab + (long long)lr * lda + kt * BK + lk;
        const float* Bg = Bb + (long long)lr * ldb + kt * BK + lk;
        #pragma unroll
        for (int c = 0; c < 4; ++c) {
            cp16(As + (lr + 32 * c) * A_STRIDE + lk, Ag + 32LL * c * lda);
            cp16(Bs + (lr + 32 * c) * A_STRIDE + lk, Bg + 32LL * c * ldb);
        }
        cp_commit();
    };

    auto compute = [&](int kt) {
        const float* As = dynsmem + (kt % STAGES) * STAGE_NT;
        const float* Bs = As + A_F;
        #pragma unroll
        for (int kk = 0; kk < BK; kk += 8) {
            uint32_t ah[4][4], al[4][4];
            #pragma unroll
            for (int i = 0; i < 4; ++i) {
                const float* p = As + (wm * 64 + i * 16 + g) * A_STRIDE + kk + q;
                split_tf(p[0],                ah[i][0], al[i][0]);
                split_tf(p[8 * A_STRIDE],     ah[i][1], al[i][1]);
                split_tf(p[4],                ah[i][2], al[i][2]);
                split_tf(p[8 * A_STRIDE + 4], ah[i][3], al[i][3]);
            }
            #pragma unroll
            for (int j = 0; j < 4; ++j) {
                const float* p = Bs + (wn * 32 + j * 8 + g) * A_STRIDE + kk + q;
                uint32_t bh[2], bl[2];
                split_tf(p[0], bh[0], bl[0]);
                split_tf(p[4], bh[1], bl[1]);
                #pragma unroll
                for (int i = 0; i < 4; ++i) {
                    mma8(acc[i][j], ah[i], bh);
                    mma8(acc[i][j], al[i], bh);
                    mma8(acc[i][j], ah[i], bl);
                }
            }
        }
    };

    load_tile(0);
    load_tile(1);
    cp_wait<STAGES - 2>();
    __syncthreads();

    for (int kt = 0; kt < KT; ++kt) {
        if (kt + STAGES - 1 < KT) load_tile(kt + STAGES - 1);
        else cp_commit();
        compute(kt);
        cp_wait<STAGES - 2>();
        __syncthreads();
    }

    #pragma unroll
    for (int i = 0; i < 4; ++i) {
        const long long r0 = m0 + wm * 64 + i * 16 + g;
        #pragma unroll
        for (int j = 0; j < 4; ++j) {
            const long long c0 = n0 + wn * 32 + j * 8 + 2 * q;
            float b0 = bias ? bias[c0]     : 0.0f;
            float b1 = bias ? bias[c0 + 1] : 0.0f;
            float2 v0 = make_float2((acc[i][j][0] + b0) * scale,
                                    (acc[i][j][1] + b1) * scale);
            float2 v1 = make_float2((acc[i][j][2] + b0) * scale,
                                    (acc[i][j][3] + b1) * scale);
            *(float2*)(Cb + r0 * ldc + c0)       = v0;
            *(float2*)(Cb + (r0 + 8) * ldc + c0) = v1;
        }
    }
}

// ---------------------------------------------------------------------------
// C = A * B.  A: MxK row-major (lda), B: KxN row-major (ldb, N-contiguous).
// ---------------------------------------------------------------------------
__global__ __launch_bounds__(256) void gemm_nn_tc(
    const float* __restrict__ A, const float* __restrict__ B,
    float* __restrict__ C,
    int K, long long lda, long long ldb, long long ldc,
    long long sA, long long sB, long long sC)
{
    const int tid = threadIdx.x, lane = tid & 31, warp = tid >> 5;
    const int wm = warp & 1, wn = warp >> 1;
    const int q = lane & 3, g = lane >> 2;

    const long long m0 = (long long)blockIdx.y * BM;
    const long long n0 = (long long)blockIdx.x * BN;
    const float* Ab = A + (long long)blockIdx.z * sA + m0 * lda;
    const float* Bb = B + (long long)blockIdx.z * sB + n0;
    float*       Cb = C + (long long)blockIdx.z * sC;

    const int lr  = tid >> 3;           // A: 0..31 rows per pass
    const int lk  = (tid & 7) * 4;
    const int br  = tid >> 5;           // B: 0..7 k-rows per pass
    const int bn4 = (tid & 31) * 4;

    float acc[4][4][4];
    #pragma unroll
    for (int i = 0; i < 4; ++i)
        #pragma unroll
        for (int j = 0; j < 4; ++j)
            #pragma unroll
            for (int r = 0; r < 4; ++r) acc[i][j][r] = 0.0f;

    const int KT = K / BK;

    auto load_tile = [&](int kt) {
        float* As = dynsmem + (kt % STAGES) * STAGE_NN;
        float* Bs = As + A_F;
        const float* Ag = Ab + (long long)lr * lda + kt * BK + lk;
        const float* Bg = Bb + (long long)kt * BK * ldb;
        #pragma unroll
        for (int c = 0; c < 4; ++c) {
            cp16(As + (lr + 32 * c) * A_STRIDE + lk, Ag + 32LL * c * lda);
            cp16(Bs + (br + 8 * c) * BN_STRIDE + bn4,
                 Bg + (long long)(br + 8 * c) * ldb + bn4);
        }
        cp_commit();
    };

    auto compute = [&](int kt) {
        const float* As = dynsmem + (kt % STAGES) * STAGE_NN;
        const float* Bs = As + A_F;
        #pragma unroll
        for (int kk = 0; kk < BK; kk += 8) {
            uint32_t ah[4][4], al[4][4];
            #pragma unroll
            for (int i = 0; i < 4; ++i) {
                const float* p = As + (wm * 64 + i * 16 + g) * A_STRIDE + kk + q;
                split_tf(p[0],                ah[i][0], al[i][0]);
                split_tf(p[8 * A_STRIDE],     ah[i][1], al[i][1]);
                split_tf(p[4],                ah[i][2], al[i][2]);
                split_tf(p[8 * A_STRIDE + 4], ah[i][3], al[i][3]);
            }
            #pragma unroll
            for (int j = 0; j < 4; ++j) {
                const float* p = Bs + (kk + q) * BN_STRIDE + wn * 32 + j * 8 + g;
                uint32_t bh[2], bl[2];
                split_tf(p[0],               bh[0], bl[0]);
                split_tf(p[4 * BN_STRIDE],   bh[1], bl[1]);
                #pragma unroll
                for (int i = 0; i < 4; ++i) {
                    mma8(acc[i][j], ah[i], bh);
                    mma8(acc[i][j], al[i], bh);
                    mma8(acc[i][j], ah[i], bl);
                }
            }
        }
    };

    load_tile(0);
    load_tile(1);
    cp_wait<STAGES - 2>();
    __syncthreads();

    for (int kt = 0; kt < KT; ++kt) {
        if (kt + STAGES - 1 < KT) load_tile(kt + STAGES - 1);
        else cp_commit();
        compute(kt);
        cp_wait<STAGES - 2>();
        __syncthreads();
    }

    #pragma unroll
    for (int i = 0; i < 4; ++i) {
        const long long r0 = m0 + wm * 64 + i * 16 + g;
        #pragma unroll
        for (int j = 0; j < 4; ++j) {
            const long long c0 = n0 + wn * 32 + j * 8 + 2 * q;
            *(float2*)(Cb + r0 * ldc + c0) =
                make_float2(acc[i][j][0], acc[i][j][1]);
            *(float2*)(Cb + (r0 + 8) * ldc + c0) =
                make_float2(acc[i][j][2], acc[i][j][3]);
        }
    }
}

// ---------------------------------------------------------------------------
// Row softmax over S_DIM=1024, one block (256 threads) per row, in place.
// ---------------------------------------------------------------------------
__global__ __launch_bounds__(256) void softmax_kernel(float* __restrict__ scores)
{
    const long long row = blockIdx.x;
    float* p = scores + row * (long long)S_DIM;
    const int t = threadIdx.x;

    float4 v = ((const float4*)p)[t];

    float m = fmaxf(fmaxf(v.x, v.y), fmaxf(v.z, v.w));
    #pragma unroll
    for (int o = 16; o > 0; o >>= 1)
        m = fmaxf(m, __shfl_xor_sync(0xFFFFFFFFu, m, o));
    __shared__ float smax[8];
    __shared__ float ssum[8];
    if ((t & 31) == 0) smax[t >> 5] = m;
    __syncthreads();
    float rowmax = smax[0];
    #pragma unroll
    for (int i = 1; i < 8; ++i) rowmax = fmaxf(rowmax, smax[i]);

    v.x = expf(v.x - rowmax);
    v.y = expf(v.y - rowmax);
    v.z = expf(v.z - rowmax);
    v.w = expf(v.w - rowmax);
    float s = v.x + v.y + v.z + v.w;
    #pragma unroll
    for (int o = 16; o > 0; o >>= 1)
        s += __shfl_xor_sync(0xFFFFFFFFu, s, o);
    if ((t & 31) == 0) ssum[t >> 5] = s;
    __syncthreads();
    float rowsum = 0.0f;
    #pragma unroll
    for (int i = 0; i < 8; ++i) rowsum += ssum[i];

    const float inv = 1.0f / rowsum;
    v.x *= inv; v.y *= inv; v.z *= inv; v.w *= inv;
    ((float4*)p)[t] = v;
}

// ---------------------------------------------------------------------------
// Launch
// ---------------------------------------------------------------------------
extern "C" void kernel_launch(void* const* d_in, const int* in_sizes, int n_in,
                              void* d_out, int out_size)
{
    const float* query = (const float*)d_in[0];
    const float* key   = (const float*)d_in[1];
    const float* value = (const float*)d_in[2];
    const float* wq    = (const float*)d_in[3];
    const float* wk    = (const float*)d_in[4];
    const float* wv    = (const float*)d_in[5];
    const float* bias  = (const float*)d_in[6];
    float* out = (float*)d_out;

    float *q, *k, *v, *sc;
    cudaGetSymbolAddress((void**)&q,  g_q);
    cudaGetSymbolAddress((void**)&k,  g_k);
    cudaGetSymbolAddress((void**)&v,  g_v);
    cudaGetSymbolAddress((void**)&sc, g_scores);

    const int smem_nt = STAGE_NT * STAGES * 4;   // 110592 B
    const int smem_nn = STAGE_NN * STAGES * 4;   // 107520 B
    cudaFuncSetAttribute(gemm_nt_tc,
                         cudaFuncAttributeMaxDynamicSharedMemorySize, smem_nt);
    cudaFuncSetAttribute(gemm_nn_tc,
                         cudaFuncAttributeMaxDynamicSharedMemorySize, smem_nn);

    const long long NE = (long long)N_BATCH * E_DIM;
    const long long LS = (long long)L_DIM * S_DIM;
    const float scaling = 1.0f / 32.0f;  // E^-0.5

    // Projections: M = L*N = 16384, N = E = 1024, K = E = 1024.
    {
        dim3 grid(E_DIM / BN, (L_DIM * N_BATCH) / BM, 1);
        gemm_nt_tc<<<grid, 256, smem_nt>>>(query, wq, q, bias,
                                           E_DIM, E_DIM, E_DIM, E_DIM,
                                           0, 0, 0, scaling);
        gemm_nt_tc<<<grid, 256, smem_nt>>>(key,   wk, k, bias + E_DIM,
                                           E_DIM, E_DIM, E_DIM, E_DIM,
                                           0, 0, 0, 1.0f);
        gemm_nt_tc<<<grid, 256, smem_nt>>>(value, wv, v, bias + 2 * E_DIM,
                                           E_DIM, E_DIM, E_DIM, E_DIM,
                                           0, 0, 0, 1.0f);
    }

    // scores[n] = q[:,n,:] @ k[:,n,:]^T
    {
        dim3 grid(S_DIM / BN, L_DIM / BM, N_BATCH);
        gemm_nt_tc<<<grid, 256, smem_nt>>>(q, k, sc, nullptr,
                                           E_DIM, NE, NE, S_DIM,
                                           E_DIM, E_DIM, LS, 1.0f);
    }

    softmax_kernel<<<N_BATCH * L_DIM, 256>>>(sc);

    // out[:,n,:] = attn[n] @ v[:,n,:]
    {
        dim3 grid(E_DIM / BN, L_DIM / BM, N_BATCH);
        gemm_nn_tc<<<grid, 256, smem_nn>>>(sc, v, out,
                                           S_DIM, S_DIM, NE, NE,
                                           LS, E_DIM, E_DIM);
    }
}

// round 4
// speedup vs baseline: 2.7204x; 1.5444x over previous
#include <cuda_runtime.h>
#include <cuda_fp16.h>
#include <cstdint>

// ---------------------------------------------------------------------------
// CLIPDecoder_83786222011049 — single-head MHA forward.
// Round 4: mma.sync m16n8k16 f16 with 3-term hi/lo split (tf32-class
// accuracy, 2x tensor throughput), operands pre-split in memory-bound
// kernels (no inner-loop cvt), cp.async 3-stage pipeline, 128x128x32 tiles.
// ---------------------------------------------------------------------------

static constexpr int L_DIM = 1024, NB = 16, E_DIMC = 1024;
static constexpr long long ME = (long long)L_DIM * NB;   // 16384

static constexpr int BM = 128, BN = 128, BK = 32, STAGES = 3;
static constexpr int SA = 40;                      // halves per SMEM row (80B)
static constexpr int TILE_B  = 128 * SA * 2;       // 10240 B per matrix-half
static constexpr int AH_O = 0, AL_O = TILE_B, BH_O = 2 * TILE_B, BL_O = 3 * TILE_B;
static constexpr int STAGE_B = 4 * TILE_B;         // 40960
static constexpr int SMEM_REQ = STAGES * STAGE_B;  // 122880

// ---------------------------------------------------------------------------
// Scratch (device globals).
// ---------------------------------------------------------------------------
#define BIGH (size_t)(16384) * 1024
#define BATH (size_t)(16) * 1024 * 1024
__device__ __align__(256) __half g_xq_h[BIGH], g_xq_l[BIGH];
__device__ __align__(256) __half g_xk_h[BIGH], g_xk_l[BIGH];
__device__ __align__(256) __half g_xv_h[BIGH], g_xv_l[BIGH];
__device__ __align__(256) __half g_wq_h[1024*1024], g_wq_l[1024*1024];
__device__ __align__(256) __half g_wk_h[1024*1024], g_wk_l[1024*1024];
__device__ __align__(256) __half g_wv_h[1024*1024], g_wv_l[1024*1024];
__device__ __align__(256) __half g_q_h[BIGH], g_q_l[BIGH];
__device__ __align__(256) __half g_k_h[BIGH], g_k_l[BIGH];
__device__ __align__(256) float  g_v[BIGH];
__device__ __align__(256) __half g_vt_h[BATH], g_vt_l[BATH];
__device__ __align__(256) float  g_scores[BATH];
__device__ __align__(256) __half g_a_h[BATH], g_a_l[BATH];

// ---------------------------------------------------------------------------
// PTX helpers
// ---------------------------------------------------------------------------
__device__ __forceinline__ void cp16(uint32_t sdst, const void* gsrc) {
    asm volatile("cp.async.cg.shared.global [%0], [%1], 16;\n"
                 :: "r"(sdst), "l"(gsrc));
}
__device__ __forceinline__ void cp_commit() {
    asm volatile("cp.async.commit_group;\n" ::: "memory");
}
template <int N> __device__ __forceinline__ void cp_wait() {
    asm volatile("cp.async.wait_group %0;\n" :: "n"(N) : "memory");
}
__device__ __forceinline__ uint32_t lds32(uint32_t a) {
    uint32_t v;
    asm volatile("ld.shared.b32 %0, [%1];" : "=r"(v) : "r"(a));
    return v;
}
__device__ __forceinline__ void mma16(float* d, const uint32_t* a, const uint32_t* b) {
    asm volatile(
        "mma.sync.aligned.m16n8k16.row.col.f32.f16.f16.f32 "
        "{%0,%1,%2,%3},{%4,%5,%6,%7},{%8,%9},{%0,%1,%2,%3};\n"
        : "+f"(d[0]), "+f"(d[1]), "+f"(d[2]), "+f"(d[3])
        : "r"(a[0]), "r"(a[1]), "r"(a[2]), "r"(a[3]), "r"(b[0]), "r"(b[1]));
}
__device__ __forceinline__ uint32_t pk2h(float a, float b) {
    __half2 t = __floats2half2_rn(a, b);
    return *reinterpret_cast<uint32_t*>(&t);
}

extern __shared__ char dynsm[];

// ---------------------------------------------------------------------------
// GEMM (NT): D = Ah*Bh^T + Al*Bh^T + Ah*Bl^T.
// A: MxK k-major halves; B: NxK k-major halves. Batched via blockIdx.z.
// Epilogue: f = acc*ascale + bias; f *= scale.
//   mode 0 -> Cf (fp32);  mode 1 -> Ch/Cl (f16 hi/lo split of f).
// ---------------------------------------------------------------------------
__global__ __launch_bounds__(256) void gemm_f16(
    const __half* __restrict__ Ah, const __half* __restrict__ Al,
    const __half* __restrict__ Bh, const __half* __restrict__ Bl,
    int K, long long lda, long long ldb, long long sA, long long sB,
    int mode, float* __restrict__ Cf,
    __half* __restrict__ Ch, __half* __restrict__ Cl,
    long long ldc, long long sC, const float* __restrict__ bias,
    float ascale, float scale)
{
    const uint32_t sbase = (uint32_t)__cvta_generic_to_shared(dynsm);
    const int tid = threadIdx.x, lane = tid & 31, warp = tid >> 5;
    const int wm = warp & 1, wn = warp >> 1;      // 2 x 4 warps
    const int q = lane & 3, g = lane >> 2;

    const long long m0 = (long long)blockIdx.y * BM;
    const long long n0 = (long long)blockIdx.x * BN;
    const long long bz = blockIdx.z;

    const char* Ahb = (const char*)(Ah + bz * sA + m0 * lda);
    const char* Alb = (const char*)(Al + bz * sA + m0 * lda);
    const char* Bhb = (const char*)(Bh + bz * sB + n0 * ldb);
    const char* Blb = (const char*)(Bl + bz * sB + n0 * ldb);

    float acc[4][4][4];
    #pragma unroll
    for (int i = 0; i < 4; ++i)
        #pragma unroll
        for (int j = 0; j < 4; ++j)
            #pragma unroll
            for (int r = 0; r < 4; ++r) acc[i][j][r] = 0.0f;

    const int KT = K / BK;
    const long long lda2 = lda * 2, ldb2 = ldb * 2;

    auto load_tile = [&](int kt) {
        const uint32_t sb = sbase + (kt % STAGES) * STAGE_B;
        const long long kb = (long long)kt * (BK * 2);   // byte offset in K
        const int row = tid >> 2, c = (tid & 3) * 16;
        #pragma unroll
        for (int p = 0; p < 2; ++p) {
            const int r = row + p * 64;
            const uint32_t d = (uint32_t)(r * 80 + c);
            const long long ga = (long long)r * lda2 + kb + c;
            const long long gb = (long long)r * ldb2 + kb + c;
            cp16(sb + AH_O + d, Ahb + ga);
            cp16(sb + AL_O + d, Alb + ga);
            cp16(sb + BH_O + d, Bhb + gb);
            cp16(sb + BL_O + d, Blb + gb);
        }
        cp_commit();
    };

    auto compute = [&](int kt) {
        const uint32_t sb = sbase + (kt % STAGES) * STAGE_B;
        #pragma unroll
        for (int kk = 0; kk < 2; ++kk) {
            const uint32_t kof = kk * 32 + q * 4;    // (16*kk + 2q) halves
            uint32_t ah[4][4], al[4][4];
            #pragma unroll
            for (int i = 0; i < 4; ++i) {
                const uint32_t o = sb + (uint32_t)((wm * 64 + i * 16 + g) * 80) + kof;
                ah[i][0] = lds32(o + AH_O);       ah[i][1] = lds32(o + AH_O + 640);
                ah[i][2] = lds32(o + AH_O + 16);  ah[i][3] = lds32(o + AH_O + 656);
                al[i][0] = lds32(o + AL_O);       al[i][1] = lds32(o + AL_O + 640);
                al[i][2] = lds32(o + AL_O + 16);  al[i][3] = lds32(o + AL_O + 656);
            }
            uint32_t bh[4][2], bl[4][2];
            #pragma unroll
            for (int j = 0; j < 4; ++j) {
                const uint32_t o = sb + (uint32_t)((wn * 32 + j * 8 + g) * 80) + kof;
                bh[j][0] = lds32(o + BH_O);  bh[j][1] = lds32(o + BH_O + 16);
                bl[j][0] = lds32(o + BL_O);  bl[j][1] = lds32(o + BL_O + 16);
            }
            #pragma unroll
            for (int i = 0; i < 4; ++i)
                #pragma unroll
                for (int j = 0; j < 4; ++j) {
                    mma16(acc[i][j], ah[i], bh[j]);
                    mma16(acc[i][j], al[i], bh[j]);
                    mma16(acc[i][j], ah[i], bl[j]);
                }
        }
    };

    load_tile(0);
    load_tile(1);
    cp_wait<1>();
    __syncthreads();

    for (int kt = 0; kt < KT; ++kt) {
        if (kt + 2 < KT) load_tile(kt + 2);
        else             cp_commit();
        compute(kt);
        cp_wait<1>();
        __syncthreads();
    }

    // ---- epilogue ----
    #pragma unroll
    for (int i = 0; i < 4; ++i) {
        const long long r0 = m0 + wm * 64 + i * 16 + g;
        #pragma unroll
        for (int j = 0; j < 4; ++j) {
            const long long c0 = n0 + wn * 32 + j * 8 + 2 * q;
            const float b0 = bias ? bias[c0]     : 0.0f;
            const float b1 = bias ? bias[c0 + 1] : 0.0f;
            float x0 = (acc[i][j][0] * ascale + b0) * scale;
            float x1 = (acc[i][j][1] * ascale + b1) * scale;
            float x2 = (acc[i][j][2] * ascale + b0) * scale;
            float x3 = (acc[i][j][3] * ascale + b1) * scale;
            if (mode == 0) {
                *(float2*)(Cf + bz * sC + r0 * ldc + c0)       = make_float2(x0, x1);
                *(float2*)(Cf + bz * sC + (r0 + 8) * ldc + c0) = make_float2(x2, x3);
            } else {
                __half h0 = __float2half_rn(x0), h1 = __float2half_rn(x1);
                __half h2 = __float2half_rn(x2), h3 = __float2half_rn(x3);
                float l0 = x0 - __half2float(h0), l1 = x1 - __half2float(h1);
                float l2 = x2 - __half2float(h2), l3 = x3 - __half2float(h3);
                *(uint32_t*)(Ch + bz * sC + r0 * ldc + c0)       = pk2h(x0, x1);
                *(uint32_t*)(Ch + bz * sC + (r0 + 8) * ldc + c0) = pk2h(x2, x3);
                *(uint32_t*)(Cl + bz * sC + r0 * ldc + c0)       = pk2h(l0, l1);
                *(uint32_t*)(Cl + bz * sC + (r0 + 8) * ldc + c0) = pk2h(l2, l3);
            }
        }
    }
}

// ---------------------------------------------------------------------------
// fp32 -> (hi, lo) f16 split of x*scale, elementwise.
// ---------------------------------------------------------------------------
__global__ __launch_bounds__(256) void split_kernel(
    const float* __restrict__ x, __half* __restrict__ h,
    __half* __restrict__ l, float scale)
{
    const long long i = (long long)blockIdx.x * 256 + threadIdx.x;
    float4 v = ((const float4*)x)[i];
    v.x *= scale; v.y *= scale; v.z *= scale; v.w *= scale;
    __half h0 = __float2half_rn(v.x), h1 = __float2half_rn(v.y);
    __half h2 = __float2half_rn(v.z), h3 = __float2half_rn(v.w);
    float l0 = v.x - __half2float(h0), l1 = v.y - __half2float(h1);
    float l2 = v.z - __half2float(h2), l3 = v.w - __half2float(h3);
    ((uint2*)h)[i] = make_uint2(pk2h(v.x, v.y), pk2h(v.z, v.w));
    ((uint2*)l)[i] = make_uint2(pk2h(l0, l1), pk2h(l2, l3));
}

// ---------------------------------------------------------------------------
// Transpose + split V:  v[(s*16+nb)*1024 + f] (fp32) -> vt{h,l}[nb][f][s]
// ---------------------------------------------------------------------------
__global__ __launch_bounds__(256) void transpose_split_kernel(
    const float* __restrict__ v, __half* __restrict__ vth,
    __half* __restrict__ vtl)
{
    __shared__ float t[64][65];
    const int nb = blockIdx.z;
    const int s0 = blockIdx.x * 64, f0 = blockIdx.y * 64;
    const int c = threadIdx.x & 63, r0 = threadIdx.x >> 6;

    #pragma unroll
    for (int rr = r0; rr < 64; rr += 4)
        t[rr][c] = v[(long long)((s0 + rr) * 16 + nb) * 1024 + f0 + c];
    __syncthreads();

    __half* oh = vth + (size_t)nb * 1024 * 1024;
    __half* ol = vtl + (size_t)nb * 1024 * 1024;
    #pragma unroll
    for (int rr = r0; rr < 64; rr += 4) {
        float x = t[c][rr];
        __half h = __float2half_rn(x);
        float lo = x - __half2float(h);
        size_t idx = (size_t)(f0 + rr) * 1024 + s0 + c;
        oh[idx] = h;
        ol[idx] = __float2half_rn(lo);
    }
}

// ---------------------------------------------------------------------------
// Row softmax over 1024 + f16 split of 256*p (keeps lo limbs normal-range).
// ---------------------------------------------------------------------------
__global__ __launch_bounds__(256) void softmax_split_kernel(
    const float* __restrict__ scores, __half* __restrict__ ah,
    __half* __restrict__ al)
{
    const long long row = blockIdx.x;
    const float* p = scores + row * 1024;
    const int t = threadIdx.x;

    float4 v = ((const float4*)p)[t];

    float m = fmaxf(fmaxf(v.x, v.y), fmaxf(v.z, v.w));
    #pragma unroll
    for (int o = 16; o > 0; o >>= 1)
        m = fmaxf(m, __shfl_xor_sync(0xFFFFFFFFu, m, o));
    __shared__ float smax[8], ssum[8];
    if ((t & 31) == 0) smax[t >> 5] = m;
    __syncthreads();
    float rowmax = smax[0];
    #pragma unroll
    for (int i = 1; i < 8; ++i) rowmax = fmaxf(rowmax, smax[i]);

    v.x = expf(v.x - rowmax); v.y = expf(v.y - rowmax);
    v.z = expf(v.z - rowmax); v.w = expf(v.w - rowmax);
    float s = v.x + v.y + v.z + v.w;
    #pragma unroll
    for (int o = 16; o > 0; o >>= 1)
        s += __shfl_xor_sync(0xFFFFFFFFu, s, o);
    if ((t & 31) == 0) ssum[t >> 5] = s;
    __syncthreads();
    float rowsum = 0.0f;
    #pragma unroll
    for (int i = 0; i < 8; ++i) rowsum += ssum[i];

    const float inv = 256.0f / rowsum;     // scale by 256 for split range
    v.x *= inv; v.y *= inv; v.z *= inv; v.w *= inv;

    __half h0 = __float2half_rn(v.x), h1 = __float2half_rn(v.y);
    __half h2 = __float2half_rn(v.z), h3 = __float2half_rn(v.w);
    float l0 = v.x - __half2float(h0), l1 = v.y - __half2float(h1);
    float l2 = v.z - __half2float(h2), l3 = v.w - __half2float(h3);
    ((uint2*)(ah + row * 1024))[t] = make_uint2(pk2h(v.x, v.y), pk2h(v.z, v.w));
    ((uint2*)(al + row * 1024))[t] = make_uint2(pk2h(l0, l1), pk2h(l2, l3));
}

// ---------------------------------------------------------------------------
// Launch
// ---------------------------------------------------------------------------
extern "C" void kernel_launch(void* const* d_in, const int* in_sizes, int n_in,
                              void* d_out, int out_size)
{
    const float* query = (const float*)d_in[0];
    const float* key   = (const float*)d_in[1];
    const float* value = (const float*)d_in[2];
    const float* wq    = (const float*)d_in[3];
    const float* wk    = (const float*)d_in[4];
    const float* wv    = (const float*)d_in[5];
    const float* bias  = (const float*)d_in[6];
    float* out = (float*)d_out;

    __half *xqh,*xql,*xkh,*xkl,*xvh,*xvl;
    __half *wqh,*wql,*wkh,*wkl,*wvh,*wvl;
    __half *qh,*ql,*kh,*kl,*vth,*vtl,*ath,*atl;
    float *vf, *sc;
    cudaGetSymbolAddress((void**)&xqh, g_xq_h); cudaGetSymbolAddress((void**)&xql, g_xq_l);
    cudaGetSymbolAddress((void**)&xkh, g_xk_h); cudaGetSymbolAddress((void**)&xkl, g_xk_l);
    cudaGetSymbolAddress((void**)&xvh, g_xv_h); cudaGetSymbolAddress((void**)&xvl, g_xv_l);
    cudaGetSymbolAddress((void**)&wqh, g_wq_h); cudaGetSymbolAddress((void**)&wql, g_wq_l);
    cudaGetSymbolAddress((void**)&wkh, g_wk_h); cudaGetSymbolAddress((void**)&wkl, g_wk_l);
    cudaGetSymbolAddress((void**)&wvh, g_wv_h); cudaGetSymbolAddress((void**)&wvl, g_wv_l);
    cudaGetSymbolAddress((void**)&qh,  g_q_h);  cudaGetSymbolAddress((void**)&ql,  g_q_l);
    cudaGetSymbolAddress((void**)&kh,  g_k_h);  cudaGetSymbolAddress((void**)&kl,  g_k_l);
    cudaGetSymbolAddress((void**)&vth, g_vt_h); cudaGetSymbolAddress((void**)&vtl, g_vt_l);
    cudaGetSymbolAddress((void**)&ath, g_a_h);  cudaGetSymbolAddress((void**)&atl, g_a_l);
    cudaGetSymbolAddress((void**)&vf,  g_v);
    cudaGetSymbolAddress((void**)&sc,  g_scores);

    cudaFuncSetAttribute(gemm_f16, cudaFuncAttributeMaxDynamicSharedMemorySize, SMEM_REQ);

    const long long MM = 1024LL * 1024;

    // 1) splits: inputs (scale 1), weights (scale 32 -> lo limbs stay normal)
    split_kernel<<<16384, 256>>>(query, xqh, xql, 1.0f);
    split_kernel<<<16384, 256>>>(key,   xkh, xkl, 1.0f);
    split_kernel<<<16384, 256>>>(value, xvh, xvl, 1.0f);
    split_kernel<<<1024,  256>>>(wq, wqh, wql, 32.0f);
    split_kernel<<<1024,  256>>>(wk, wkh, wkl, 32.0f);
    split_kernel<<<1024,  256>>>(wv, wvh, wvl, 32.0f);

    // 2) projections (M=16384, N=1024, K=1024); ascale=1/32 undoes weight x32.
    //    q is written UNSCALED (E^-0.5 applied at the scores epilogue).
    {
        dim3 grid(1024 / BN, ME / BM, 1);
        gemm_f16<<<grid, 256, SMEM_REQ>>>(xqh, xql, wqh, wql, 1024, 1024, 1024, 0, 0,
                                          1, nullptr, qh, ql, 1024, 0,
                                          bias, 1.0f / 32.0f, 1.0f);
        gemm_f16<<<grid, 256, SMEM_REQ>>>(xkh, xkl, wkh, wkl, 1024, 1024, 1024, 0, 0,
                                          1, nullptr, kh, kl, 1024, 0,
                                          bias + 1024, 1.0f / 32.0f, 1.0f);
        gemm_f16<<<grid, 256, SMEM_REQ>>>(xvh, xvl, wvh, wvl, 1024, 1024, 1024, 0, 0,
                                          0, vf, nullptr, nullptr, 1024, 0,
                                          bias + 2048, 1.0f / 32.0f, 1.0f);
    }

    // 3) V transpose + split -> vt[nb][f][s]
    {
        dim3 grid(16, 16, 16);
        transpose_split_kernel<<<grid, 256>>>(vf, vth, vtl);
    }

    // 4) scores[nb] = (q[:,nb,:] @ k[:,nb,:]^T) * E^-0.5
    {
        dim3 grid(1024 / BN, 1024 / BM, 16);
        gemm_f16<<<grid, 256, SMEM_REQ>>>(qh, ql, kh, kl, 1024,
                                          16384, 16384, 1024, 1024,
                                          0, sc, nullptr, nullptr,
                                          1024, MM, nullptr, 1.0f, 1.0f / 32.0f);
    }

    // 5) softmax + split (outputs scaled x256)
    softmax_split_kernel<<<16 * 1024, 256>>>(sc, ath, atl);

    // 6) out[l][nb][f] = attn[nb] @ vt[nb]^T ; ascale=1/256 undoes attn x256
    {
        dim3 grid(1024 / BN, 1024 / BM, 16);
        gemm_f16<<<grid, 256, SMEM_REQ>>>(ath, atl, vth, vtl, 1024,
                                          1024, 1024, MM, MM,
                                          0, out, nullptr, nullptr,
                                          16384, 1024, nullptr, 1.0f / 256.0f, 1.0f);
    }
}